// round 12
// baseline (speedup 1.0000x reference)
#include <cuda_runtime.h>
#include <cuda_fp16.h>
#include <cstdint>
#include <math.h>

#define BB 8
#define SS 512
#define DD 256
#define NPAIRS (SS * (SS - 1) / 2)   // 130816
#define TILE 64
#define NTRI 36                      // lower-tri 64x64 tiles per batch
#define KC 128                       // K per smem chunk (256B rows)

// ---- device globals (no cudaMalloc allowed) ----
__device__ float g_norms[BB * SS];
__device__ __align__(16) __half g_h[BB * SS * DD];   // fp16(x), 2MB

// tile index LUT: (ti<<4)|tj for t in [0,36)
__device__ const uint8_t c_tij[NTRI] = {
    0x00,
    0x10, 0x11,
    0x20, 0x21, 0x22,
    0x30, 0x31, 0x32, 0x33,
    0x40, 0x41, 0x42, 0x43, 0x44,
    0x50, 0x51, 0x52, 0x53, 0x54, 0x55,
    0x60, 0x61, 0x62, 0x63, 0x64, 0x65, 0x66,
    0x70, 0x71, 0x72, 0x73, 0x74, 0x75, 0x76, 0x77
};

// ---------------------------------------------------------------------------
__device__ __forceinline__ uint32_t smem_u32(const void* p) {
    uint32_t a;
    asm("{ .reg .u64 t; cvta.to.shared.u64 t, %1; cvt.u32.u64 %0, t; }" : "=r"(a) : "l"(p));
    return a;
}
__device__ __forceinline__ void cp_async16(uint32_t dst, const void* src) {
    asm volatile("cp.async.cg.shared.global [%0], [%1], 16;" :: "r"(dst), "l"(src) : "memory");
}
__device__ __forceinline__ void cp_commit() { asm volatile("cp.async.commit_group;" ::: "memory"); }
__device__ __forceinline__ void ldm_x4(uint32_t& r0, uint32_t& r1, uint32_t& r2, uint32_t& r3,
                                       uint32_t addr) {
    asm volatile("ldmatrix.sync.aligned.m8n8.x4.shared.b16 {%0,%1,%2,%3}, [%4];"
                 : "=r"(r0), "=r"(r1), "=r"(r2), "=r"(r3) : "r"(addr));
}
__device__ __forceinline__ void mma_f16(float* d, const uint32_t* a, const uint32_t* bfr) {
    asm volatile(
        "mma.sync.aligned.m16n8k16.row.col.f32.f16.f16.f32 "
        "{%0,%1,%2,%3}, {%4,%5,%6,%7}, {%8,%9}, {%0,%1,%2,%3};"
        : "+f"(d[0]), "+f"(d[1]), "+f"(d[2]), "+f"(d[3])
        : "r"(a[0]), "r"(a[1]), "r"(a[2]), "r"(a[3]), "r"(bfr[0]), "r"(bfr[1]));
}
__device__ __forceinline__ float sqrt_approx(float v) {
    float r;
    asm("sqrt.approx.f32 %0, %1;" : "=f"(r) : "f"(v));
    return r;
}

// ---------------------------------------------------------------------------
// Kernel 1: per-row norms (exact fp32) + fp16 conversion. One warp per row.
// ---------------------------------------------------------------------------
__global__ __launch_bounds__(256) void prep_kernel(const float* __restrict__ x) {
    int row = blockIdx.x * 8 + (threadIdx.x >> 5);
    int lane = threadIdx.x & 31;
    if (row >= BB * SS) return;
    const float4* x4 = reinterpret_cast<const float4*>(x) + (size_t)row * (DD / 4);
    float4 a = x4[lane];
    float4 c = x4[lane + 32];
    float s = a.x * a.x + a.y * a.y + a.z * a.z + a.w * a.w
            + c.x * c.x + c.y * c.y + c.z * c.z + c.w * c.w;
#pragma unroll
    for (int o = 16; o; o >>= 1) s += __shfl_xor_sync(0xFFFFFFFFu, s, o);
    if (lane == 0) g_norms[row] = s;

    size_t base = (size_t)row * DD;
#pragma unroll
    for (int g = 0; g < 2; ++g) {
        float4 v = g ? c : a;
        __half2 h0 = __floats2half2_rn(v.x, v.y);
        __half2 h1 = __floats2half2_rn(v.z, v.w);
        uint2 hv = make_uint2(*(uint32_t*)&h0, *(uint32_t*)&h1);
        *reinterpret_cast<uint2*>(g_h + base + g * 128 + lane * 4) = hv;
    }
}

// ---------------------------------------------------------------------------
// Kernel 2 (R5 config + diag work-skip): 64x64 Gram tile per CTA, 4 warps
// (2x2, warp tile 32x32). K=256 in 2 chunks of 128 (256B rows, XOR-16B
// swizzle), both cp.async groups issued upfront to separate buffers;
// fp32-accumulate mma.sync; register-pipelined ldmatrix.
// DIAG path: B aliases A (half the loads), MMA frags fully above the strict
// diagonal are skipped (37.5% of diag-tile HMMAs). sqrt.approx epilogue.
// ---------------------------------------------------------------------------
#define SM_NORM 512
#define MAT_BYTES 16384              // 64 rows x 256B
#define BUF_BYTES (2 * MAT_BYTES)
#define SMEM_TOTAL (SM_NORM + 2 * BUF_BYTES)

template <bool DIAG>
__device__ __forceinline__ void tile_body(
    uint32_t sbase, int lane, int wtm, int wtn, int ti, int tj,
    const float* si, const float* sjn, float* __restrict__ ob) {

    // per-lane ldmatrix addressing (row stride 256B, 16 slots/row)
    int rA = lane & 15;
    int kselA = (lane >> 4) & 1;
    int rB = (lane & 7) | ((lane >> 1) & 8);
    int kselB = (lane >> 3) & 1;
    uint32_t aRow = sbase + SM_NORM + (wtm * 32 + rA) * 256;
    uint32_t bRow = sbase + SM_NORM + (DIAG ? 0 : MAT_BYTES) + (wtn * 32 + rB) * 256;

    float acc[2][4][4];
#pragma unroll
    for (int mt = 0; mt < 2; ++mt)
#pragma unroll
        for (int nt = 0; nt < 4; ++nt)
#pragma unroll
            for (int e = 0; e < 4; ++e) acc[mt][nt][e] = 0.0f;

    uint32_t afr[2][2][4], bfr[2][2][4];  // [pipe][mt|nh][frag]
    auto load_frags = [&](int p, int bufi, int ks) {
        uint32_t bo = bufi * BUF_BYTES;
        uint32_t swA = ((ks * 2 + kselA) ^ (rA & 7)) * 16;
        uint32_t swB = ((ks * 2 + kselB) ^ (rB & 7)) * 16;
#pragma unroll
        for (int mt = 0; mt < 2; ++mt)
            ldm_x4(afr[p][mt][0], afr[p][mt][1], afr[p][mt][2], afr[p][mt][3],
                   aRow + bo + mt * 4096 + swA);
#pragma unroll
        for (int nh = 0; nh < 2; ++nh)
            ldm_x4(bfr[p][nh][0], bfr[p][nh][1], bfr[p][nh][2], bfr[p][nh][3],
                   bRow + bo + nh * 4096 + swB);
    };
    auto do_mma = [&](int p) {
#pragma unroll
        for (int mt = 0; mt < 2; ++mt)
#pragma unroll
            for (int nt = 0; nt < 4; ++nt) {
                if (DIAG) {
                    // frag rows r0 = 32*wtm + 16*mt, cols c0 = 32*wtn + 8*nt;
                    // skip if entirely above strict diagonal (c0 >= r0 + 16)
                    if (32 * wtn + 8 * nt >= 32 * wtm + 16 * mt + 16) continue;
                }
                uint32_t bb2[2] = { bfr[p][nt >> 1][(nt & 1) * 2],
                                    bfr[p][nt >> 1][(nt & 1) * 2 + 1] };
                mma_f16(acc[mt][nt], afr[p][mt], bb2);
            }
    };

    // chunk 0 ready (group for chunk1 still pending)
    asm volatile("cp.async.wait_group 1;" ::: "memory");
    __syncthreads();

    load_frags(0, 0, 0);
#pragma unroll
    for (int ks = 0; ks < 8; ++ks) {
        if (ks < 7) load_frags((ks + 1) & 1, 0, ks + 1);
        do_mma(ks & 1);
    }

    // chunk 1 ready
    asm volatile("cp.async.wait_group 0;" ::: "memory");
    __syncthreads();

    load_frags(0, 1, 0);
#pragma unroll
    for (int ks = 0; ks < 8; ++ks) {
        if (ks < 7) load_frags((ks + 1) & 1, 1, ks + 1);
        do_mma(ks & 1);
    }

    // ---- epilogue ----
    int lr = lane >> 2;            // 0..7
    int lc = 2 * (lane & 3);       // 0,2,4,6
#pragma unroll
    for (int mt = 0; mt < 2; ++mt) {
        int r0 = wtm * 32 + mt * 16 + lr;
        int i0 = ti * TILE + r0;
        int i1 = i0 + 8;
        float n0 = si[r0], n1 = si[r0 + 8];
        int base0 = i0 * (i0 - 1) / 2;
        int base1 = i1 * (i1 - 1) / 2;
#pragma unroll
        for (int nt = 0; nt < 4; ++nt) {
            if (DIAG) {
                if (32 * wtn + 8 * nt >= 32 * wtm + 16 * mt + 16) continue;
            }
            int col = wtn * 32 + nt * 8 + lc;
            int j = tj * TILE + col;
            float njc0 = sjn[col], njc1 = sjn[col + 1];
            float* c = acc[mt][nt];
            if (j < i0)     ob[base0 + j]     = sqrt_approx(fmaxf(n0 + njc0 - 2.0f * c[0], 1e-7f));
            if (j + 1 < i0) ob[base0 + j + 1] = sqrt_approx(fmaxf(n0 + njc1 - 2.0f * c[1], 1e-7f));
            if (j < i1)     ob[base1 + j]     = sqrt_approx(fmaxf(n1 + njc0 - 2.0f * c[2], 1e-7f));
            if (j + 1 < i1) ob[base1 + j + 1] = sqrt_approx(fmaxf(n1 + njc1 - 2.0f * c[3], 1e-7f));
        }
    }
}

__global__ __launch_bounds__(128, 2) void dist_kernel(float* __restrict__ out) {
    extern __shared__ char smem[];
    uint32_t sbase = smem_u32(smem);
    int tid = threadIdx.x;
    int lane = tid & 31;
    int wid = tid >> 5;
    int wtm = wid >> 1;  // 0..1 -> m offset 32*wtm
    int wtn = wid & 1;   // 0..1 -> n offset 32*wtn

    int b = blockIdx.y;
    uint32_t tij = c_tij[blockIdx.x];
    int ti = tij >> 4;
    int tj = tij & 15;
    bool diag = (ti == tj);

    // stage norms
    float* si = reinterpret_cast<float*>(smem);          // rows (i)
    float* sjn = reinterpret_cast<float*>(smem + 256);   // cols (j)
    if (tid < 64) si[tid] = g_norms[b * SS + ti * TILE + tid];
    else if (tid < 128) sjn[tid - 64] = g_norms[b * SS + tj * TILE + (tid - 64)];

    // loader geometry: kk = tid&15 (16B chunk of a 256B row-chunk), row8 = tid>>4
    int kk = tid & 15, row8 = tid >> 4;
    const __half* pAg = g_h + ((size_t)(b * SS + ti * TILE) + row8) * DD + kk * 8;
    const __half* pBg = g_h + ((size_t)(b * SS + tj * TILE) + row8) * DD + kk * 8;
    uint32_t dA = sbase + SM_NORM + row8 * 256 + ((kk ^ (row8 & 7)) * 16);
    uint32_t dB = dA + MAT_BYTES;

    // both chunks issued upfront to separate buffers (no reuse)
#pragma unroll
    for (int ch = 0; ch < 2; ++ch) {
        uint32_t bo = ch * BUF_BYTES;
        const __half* sa = pAg + ch * KC;
        const __half* sb = pBg + ch * KC;
#pragma unroll
        for (int q = 0; q < 8; ++q) {   // rows row8 + 8q
            cp_async16(dA + bo + q * 2048, sa + (size_t)q * 8 * DD);
            if (!diag) cp_async16(dB + bo + q * 2048, sb + (size_t)q * 8 * DD);
        }
        cp_commit();
    }

    float* ob = out + (size_t)b * NPAIRS;
    if (diag)
        tile_body<true>(sbase, lane, wtm, wtn, ti, tj, si, si, ob);
    else
        tile_body<false>(sbase, lane, wtm, wtn, ti, tj, si, sjn, ob);
}

// ---------------------------------------------------------------------------
extern "C" void kernel_launch(void* const* d_in, const int* in_sizes, int n_in,
                              void* d_out, int out_size) {
    const float* x = (const float*)d_in[0];
    float* out = (float*)d_out;

    static bool attr_done = false;
    if (!attr_done) {
        cudaFuncSetAttribute(dist_kernel, cudaFuncAttributeMaxDynamicSharedMemorySize,
                             SMEM_TOTAL);
        attr_done = true;
    }

    prep_kernel<<<512, 256>>>(x);

    dim3 grid(NTRI, BB);
    dist_kernel<<<grid, 128, SMEM_TOTAL>>>(out);
}

// round 13
// speedup vs baseline: 1.4048x; 1.4048x over previous
#include <cuda_runtime.h>
#include <cuda_fp16.h>
#include <cstdint>
#include <math.h>

#define BB 8
#define SS 512
#define DD 256
#define NPAIRS (SS * (SS - 1) / 2)   // 130816
#define TILE 64
#define NT (SS / TILE)               // 8
#define NTRI (NT * (NT + 1) / 2)     // 36 lower-tri 64x64 tiles per batch
#define KC 128                       // K per smem chunk (256B rows)

// ---- device globals (no cudaMalloc allowed) ----
__device__ float g_norms[BB * SS];
__device__ __align__(16) __half g_h[BB * SS * DD];   // fp16(x), 2MB

// ---------------------------------------------------------------------------
__device__ __forceinline__ uint32_t smem_u32(const void* p) {
    uint32_t a;
    asm("{ .reg .u64 t; cvta.to.shared.u64 t, %1; cvt.u32.u64 %0, t; }" : "=r"(a) : "l"(p));
    return a;
}
__device__ __forceinline__ void cp_async16(uint32_t dst, const void* src) {
    asm volatile("cp.async.cg.shared.global [%0], [%1], 16;" :: "r"(dst), "l"(src) : "memory");
}
__device__ __forceinline__ void cp_commit() { asm volatile("cp.async.commit_group;" ::: "memory"); }
__device__ __forceinline__ void ldm_x4(uint32_t& r0, uint32_t& r1, uint32_t& r2, uint32_t& r3,
                                       uint32_t addr) {
    asm volatile("ldmatrix.sync.aligned.m8n8.x4.shared.b16 {%0,%1,%2,%3}, [%4];"
                 : "=r"(r0), "=r"(r1), "=r"(r2), "=r"(r3) : "r"(addr));
}
__device__ __forceinline__ void mma_f16(float* d, const uint32_t* a, const uint32_t* bfr) {
    asm volatile(
        "mma.sync.aligned.m16n8k16.row.col.f32.f16.f16.f32 "
        "{%0,%1,%2,%3}, {%4,%5,%6,%7}, {%8,%9}, {%0,%1,%2,%3};"
        : "+f"(d[0]), "+f"(d[1]), "+f"(d[2]), "+f"(d[3])
        : "r"(a[0]), "r"(a[1]), "r"(a[2]), "r"(a[3]), "r"(bfr[0]), "r"(bfr[1]));
}
__device__ __forceinline__ float sqrt_approx(float v) {
    float r;
    asm("sqrt.approx.f32 %0, %1;" : "=f"(r) : "f"(v));
    return r;
}

// ---------------------------------------------------------------------------
// Kernel 1: per-row norms (exact fp32) + fp16 conversion. One warp per row.
// ---------------------------------------------------------------------------
__global__ __launch_bounds__(256) void prep_kernel(const float* __restrict__ x) {
    int row = blockIdx.x * 8 + (threadIdx.x >> 5);
    int lane = threadIdx.x & 31;
    if (row >= BB * SS) return;
    const float4* x4 = reinterpret_cast<const float4*>(x) + (size_t)row * (DD / 4);
    float4 a = x4[lane];
    float4 c = x4[lane + 32];
    float s = a.x * a.x + a.y * a.y + a.z * a.z + a.w * a.w
            + c.x * c.x + c.y * c.y + c.z * c.z + c.w * c.w;
#pragma unroll
    for (int o = 16; o; o >>= 1) s += __shfl_xor_sync(0xFFFFFFFFu, s, o);
    if (lane == 0) g_norms[row] = s;

    size_t base = (size_t)row * DD;
#pragma unroll
    for (int g = 0; g < 2; ++g) {
        float4 v = g ? c : a;
        __half2 h0 = __floats2half2_rn(v.x, v.y);
        __half2 h1 = __floats2half2_rn(v.z, v.w);
        uint2 hv = make_uint2(*(uint32_t*)&h0, *(uint32_t*)&h1);
        *reinterpret_cast<uint2*>(g_h + base + g * 128 + lane * 4) = hv;
    }
}

// ---------------------------------------------------------------------------
// Kernel 2 (R5 configuration): 64x64 Gram tile per CTA, 4 warps (2x2,
// warp tile 32x32). K=256 in 2 chunks of 128 (256B smem rows, XOR-16B
// swizzle), cp.async into separate buffers issued upfront; mma.sync
// fp16->fp32; register-pipelined ldmatrix. sqrt.approx epilogue.
// smem: si[64], sj[64] f32 (512B), then 2 bufs x (A 16KB + B 16KB).
// ---------------------------------------------------------------------------
#define SM_NORM 512
#define MAT_BYTES 16384              // 64 rows x 256B
#define BUF_BYTES (2 * MAT_BYTES)
#define SMEM_TOTAL (SM_NORM + 2 * BUF_BYTES)

__global__ __launch_bounds__(128, 2) void dist_kernel(float* __restrict__ out) {
    extern __shared__ char smem[];
    uint32_t sbase = smem_u32(smem);
    int tid = threadIdx.x;
    int lane = tid & 31;
    int wid = tid >> 5;
    int wtm = wid >> 1;  // 0..1 -> m offset 32*wtm
    int wtn = wid & 1;   // 0..1 -> n offset 32*wtn

    int b = blockIdx.y;
    int t = blockIdx.x;
    int ti = 0;
    while ((ti + 1) * (ti + 2) / 2 <= t) ti++;
    int tj = t - ti * (ti + 1) / 2;

    // stage norms
    float* si = reinterpret_cast<float*>(smem);          // rows (i)
    float* sjn = reinterpret_cast<float*>(smem + 256);   // cols (j)
    if (tid < 64) si[tid] = g_norms[b * SS + ti * TILE + tid];
    else if (tid < 128) sjn[tid - 64] = g_norms[b * SS + tj * TILE + (tid - 64)];

    // loader geometry: kk = tid&15 (16B chunk of a 256B row-chunk), row8 = tid>>4
    int kk = tid & 15, row8 = tid >> 4;
    const __half* pAg = g_h + ((size_t)(b * SS + ti * TILE) + row8) * DD + kk * 8;
    const __half* pBg = g_h + ((size_t)(b * SS + tj * TILE) + row8) * DD + kk * 8;
    uint32_t dA = sbase + SM_NORM + row8 * 256 + ((kk ^ (row8 & 7)) * 16);
    uint32_t dB = dA + MAT_BYTES;

    auto issue_chunk = [&](int ch, int bufi) {
        uint32_t bo = bufi * BUF_BYTES;
        const __half* sa = pAg + ch * KC;
        const __half* sb = pBg + ch * KC;
#pragma unroll
        for (int q = 0; q < 8; ++q) {   // rows row8 + 8q
            cp_async16(dA + bo + q * 2048, sa + (size_t)q * 8 * DD);
            cp_async16(dB + bo + q * 2048, sb + (size_t)q * 8 * DD);
        }
        cp_commit();
    };

    // per-lane ldmatrix addressing (row stride 256B, 16 slots/row)
    int rA = lane & 15;
    int kselA = (lane >> 4) & 1;
    int rB = (lane & 7) | ((lane >> 1) & 8);
    int kselB = (lane >> 3) & 1;
    uint32_t aRow = sbase + SM_NORM + (wtm * 32 + rA) * 256;
    uint32_t bRow = sbase + SM_NORM + MAT_BYTES + (wtn * 32 + rB) * 256;

    float acc[2][4][4];
#pragma unroll
    for (int mt = 0; mt < 2; ++mt)
#pragma unroll
        for (int nt = 0; nt < 4; ++nt)
#pragma unroll
            for (int e = 0; e < 4; ++e) acc[mt][nt][e] = 0.0f;

    issue_chunk(0, 0);
    issue_chunk(1, 1);

    uint32_t afr[2][2][4], bfr[2][2][4];  // [pipe][mt|nh][frag]
    auto load_frags = [&](int p, int bufi, int ks) {
        uint32_t bo = bufi * BUF_BYTES;
        uint32_t swA = ((ks * 2 + kselA) ^ (rA & 7)) * 16;
        uint32_t swB = ((ks * 2 + kselB) ^ (rB & 7)) * 16;
#pragma unroll
        for (int mt = 0; mt < 2; ++mt)
            ldm_x4(afr[p][mt][0], afr[p][mt][1], afr[p][mt][2], afr[p][mt][3],
                   aRow + bo + mt * 4096 + swA);
#pragma unroll
        for (int nh = 0; nh < 2; ++nh)
            ldm_x4(bfr[p][nh][0], bfr[p][nh][1], bfr[p][nh][2], bfr[p][nh][3],
                   bRow + bo + nh * 4096 + swB);
    };
    auto do_mma = [&](int p) {
#pragma unroll
        for (int mt = 0; mt < 2; ++mt)
#pragma unroll
            for (int nt = 0; nt < 4; ++nt) {
                uint32_t bb2[2] = { bfr[p][nt >> 1][(nt & 1) * 2],
                                    bfr[p][nt >> 1][(nt & 1) * 2 + 1] };
                mma_f16(acc[mt][nt], afr[p][mt], bb2);
            }
    };

    // chunk 0 ready
    asm volatile("cp.async.wait_group 1;" ::: "memory");
    __syncthreads();

    load_frags(0, 0, 0);
#pragma unroll
    for (int ks = 0; ks < 8; ++ks) {
        if (ks < 7) load_frags((ks + 1) & 1, 0, ks + 1);
        do_mma(ks & 1);
    }

    // chunk 1 ready
    asm volatile("cp.async.wait_group 0;" ::: "memory");
    __syncthreads();

    load_frags(0, 1, 0);
#pragma unroll
    for (int ks = 0; ks < 8; ++ks) {
        if (ks < 7) load_frags((ks + 1) & 1, 1, ks + 1);
        do_mma(ks & 1);
    }

    // ---- epilogue ----
    int lr = lane >> 2;            // 0..7
    int lc = 2 * (lane & 3);       // 0,2,4,6
    float* ob = out + (size_t)b * NPAIRS;
#pragma unroll
    for (int mt = 0; mt < 2; ++mt) {
        int r0 = wtm * 32 + mt * 16 + lr;
        int i0 = ti * TILE + r0;
        int i1 = i0 + 8;
        float n0 = si[r0], n1 = si[r0 + 8];
        int base0 = i0 * (i0 - 1) / 2;
        int base1 = i1 * (i1 - 1) / 2;
#pragma unroll
        for (int nt = 0; nt < 4; ++nt) {
            int col = wtn * 32 + nt * 8 + lc;
            int j = tj * TILE + col;
            float njc0 = sjn[col], njc1 = sjn[col + 1];
            float* c = acc[mt][nt];
            if (j < i0)     ob[base0 + j]     = sqrt_approx(fmaxf(n0 + njc0 - 2.0f * c[0], 1e-7f));
            if (j + 1 < i0) ob[base0 + j + 1] = sqrt_approx(fmaxf(n0 + njc1 - 2.0f * c[1], 1e-7f));
            if (j < i1)     ob[base1 + j]     = sqrt_approx(fmaxf(n1 + njc0 - 2.0f * c[2], 1e-7f));
            if (j + 1 < i1) ob[base1 + j + 1] = sqrt_approx(fmaxf(n1 + njc1 - 2.0f * c[3], 1e-7f));
        }
    }
}

// ---------------------------------------------------------------------------
extern "C" void kernel_launch(void* const* d_in, const int* in_sizes, int n_in,
                              void* d_out, int out_size) {
    const float* x = (const float*)d_in[0];
    float* out = (float*)d_out;

    static bool attr_done = false;
    if (!attr_done) {
        cudaFuncSetAttribute(dist_kernel, cudaFuncAttributeMaxDynamicSharedMemorySize,
                             SMEM_TOTAL);
        attr_done = true;
    }

    prep_kernel<<<512, 256>>>(x);

    dim3 grid(NTRI, BB);
    dist_kernel<<<grid, 128, SMEM_TOTAL>>>(out);
}